// round 16
// baseline (speedup 1.0000x reference)
#include <cuda_runtime.h>
#include <math.h>

#define BDIM 512
#define TDIM 512
#define IN0  64
#define HDIM 128
#define G3   384   // 3*H  (gate order r, z, n)

typedef unsigned long long u64;

// ---------------------------------------------------------------------------
// f32x2 packed helpers
// ---------------------------------------------------------------------------
__device__ __forceinline__ u64 splat2(unsigned int v) {
    u64 r; asm("mov.b64 %0, {%1, %1};" : "=l"(r) : "r"(v)); return r;
}
__device__ __forceinline__ void fma2(u64& d, u64 a, u64 b) {
    asm("fma.rn.f32x2 %0, %1, %2, %0;" : "+l"(d) : "l"(a), "l"(b));
}
__device__ __forceinline__ float2 unpack2(u64 v) {
    unsigned int lo, hi;
    asm("mov.b64 {%0, %1}, %2;" : "=r"(lo), "=r"(hi) : "l"(v));
    float2 f; f.x = __uint_as_float(lo); f.y = __uint_as_float(hi); return f;
}
__device__ __forceinline__ float sigmoid_f(float x) {
    return __fdividef(1.f, 1.f + __expf(-x));
}
__device__ __forceinline__ float tanh_f(float x) {
    // 2*sigmoid(2x) - 1 : short MUFU chain, rel err ~1e-6 (validated)
    return __fmaf_rn(2.f, __fdividef(1.f, 1.f + __expf(-2.f * x)), -1.f);
}
#define NAMED_BAR(id, cnt) asm volatile("bar.sync %0, %1;" :: "r"(id), "r"(cnt) : "memory")

// ---------------------------------------------------------------------------
// Scratch
// ---------------------------------------------------------------------------
__device__ float g_gi [(size_t)BDIM * TDIM * G3];
__device__ float g_h1 [(size_t)BDIM * TDIM * HDIM];
__device__ float g_hlast[(size_t)BDIM * HDIM];
__device__ float g_WT0[64  * G3];    // W_ih0 transposed: [K][384]
__device__ float g_WT1[128 * G3];    // W_ih1 transposed: [K][384]

// ---------------------------------------------------------------------------
// One-time W_ih transpose: WT[k][g] = W[g][k].
// ---------------------------------------------------------------------------
template <int K>
__global__ void transpose_w(const float* __restrict__ W, float* __restrict__ WT)
{
    int idx = blockIdx.x * blockDim.x + threadIdx.x;
    if (idx >= G3 * K) return;
    int g = idx / K, k = idx - g * K;
    WT[k * G3 + g] = W[idx];
}

// ---------------------------------------------------------------------------
// gi GEMM K=64 (R9-exact, 43 KB smem -> 5 CTAs/SM).
// ---------------------------------------------------------------------------
__global__ __launch_bounds__(256)
void gi_gemm64(const float* __restrict__ X,
               const float* __restrict__ WT,   // [64][384] transposed
               const float* __restrict__ bias)
{
    constexpr int K   = 64;
    constexpr int TM  = 64;
    constexpr int NC  = 96;
    constexpr int XP  = K + 4;
    constexpr int WP2 = 100;

    extern __shared__ float sm[];
    float* xs = sm;               // [TM][XP] row-major
    float* ws = sm + TM * XP;     // [K][WP2]; reused as [64][96] staging

    const int tid = threadIdx.x;
    const int rowbase = blockIdx.x * TM;

    for (int idx = tid; idx < TM * (K / 4); idx += 256) {
        int r = idx / (K / 4), kb = idx - r * (K / 4);
        float4 v = *(const float4*)&X[(size_t)(rowbase + r) * K + kb * 4];
        *(float4*)&xs[r * XP + kb * 4] = v;
    }

    const int rg = tid >> 4;
    const int gg = tid & 15;
    float* out = g_gi;

    for (int c = 0; c < 4; ++c) {
        __syncthreads();
        for (int idx = tid; idx < K * (NC / 4); idx += 256) {
            int k = idx / (NC / 4), g4 = idx - k * (NC / 4);
            float4 v = *(const float4*)&WT[(size_t)k * G3 + c * NC + g4 * 4];
            *(float4*)&ws[k * WP2 + g4 * 4] = v;
        }
        __syncthreads();

        u64 acc[4][3];
        #pragma unroll
        for (int i = 0; i < 4; ++i)
            #pragma unroll
            for (int p = 0; p < 3; ++p) acc[i][p] = 0ull;

        const float* xr0 = &xs[(rg * 4 + 0) * XP];
        const float* xr1 = &xs[(rg * 4 + 1) * XP];
        const float* xr2 = &xs[(rg * 4 + 2) * XP];
        const float* xr3 = &xs[(rg * 4 + 3) * XP];
        const float* wp0 = &ws[gg * 6];

        #pragma unroll 4
        for (int k = 0; k < K; ++k) {
            u64 x0 = splat2(__float_as_uint(xr0[k]));
            u64 x1 = splat2(__float_as_uint(xr1[k]));
            u64 x2 = splat2(__float_as_uint(xr2[k]));
            u64 x3 = splat2(__float_as_uint(xr3[k]));
            const u64* wrow = (const u64*)&wp0[k * WP2];
            u64 w01 = wrow[0], w23 = wrow[1], w45 = wrow[2];
            fma2(acc[0][0], x0, w01); fma2(acc[0][1], x0, w23); fma2(acc[0][2], x0, w45);
            fma2(acc[1][0], x1, w01); fma2(acc[1][1], x1, w23); fma2(acc[1][2], x1, w45);
            fma2(acc[2][0], x2, w01); fma2(acc[2][1], x2, w23); fma2(acc[2][2], x2, w45);
            fma2(acc[3][0], x3, w01); fma2(acc[3][1], x3, w23); fma2(acc[3][2], x3, w45);
        }

        __syncthreads();

        const int g0 = c * NC + gg * 6;
        #pragma unroll
        for (int p = 0; p < 3; ++p) {
            float b0 = bias[g0 + 2 * p];
            float b1 = bias[g0 + 2 * p + 1];
            #pragma unroll
            for (int i = 0; i < 4; ++i) {
                float2 v = unpack2(acc[i][p]);
                int r = rg * 4 + i;
                ws[r * NC + gg * 6 + 2 * p]     = v.x + b0;
                ws[r * NC + gg * 6 + 2 * p + 1] = v.y + b1;
            }
        }
        __syncthreads();

        #pragma unroll
        for (int v = 0; v < (TM * NC / 4) / 256; ++v) {
            int idx = (v * 256 + tid) * 4;
            int r = idx / NC, col = idx - r * NC;
            float4 val = *(const float4*)&ws[idx];
            *(float4*)&out[(size_t)(rowbase + r) * G3 + c * NC + col] = val;
        }
    }
}

// ---------------------------------------------------------------------------
// gi GEMM K=128 (R15-exact): xs staged once, ws in two 64-k halves -> 3 CTAs.
// ---------------------------------------------------------------------------
__global__ __launch_bounds__(256)
void gi_gemm128(const float* __restrict__ X,
                const float* __restrict__ WT,   // [128][384] transposed
                const float* __restrict__ bias)
{
    constexpr int K   = 128;
    constexpr int KT  = 64;
    constexpr int TM  = 64;
    constexpr int NC  = 96;
    constexpr int XP  = K + 4;       // 132
    constexpr int WP2 = 100;

    extern __shared__ float sm[];
    float* xs = sm;               // [TM][132], staged once
    float* ws = sm + TM * XP;     // [KT][WP2]; reused as staging

    const int tid = threadIdx.x;
    const int rowbase = blockIdx.x * TM;

    for (int idx = tid; idx < TM * (K / 4); idx += 256) {
        int r = idx / (K / 4), kb = idx - r * (K / 4);
        float4 v = *(const float4*)&X[(size_t)(rowbase + r) * K + kb * 4];
        *(float4*)&xs[r * XP + kb * 4] = v;
    }

    const int rg = tid >> 4;
    const int gg = tid & 15;
    float* out = g_gi;

    for (int c = 0; c < 4; ++c) {
        u64 acc[4][3];
        #pragma unroll
        for (int i = 0; i < 4; ++i)
            #pragma unroll
            for (int p = 0; p < 3; ++p) acc[i][p] = 0ull;

        const float* xr0 = &xs[(rg * 4 + 0) * XP];
        const float* xr1 = &xs[(rg * 4 + 1) * XP];
        const float* xr2 = &xs[(rg * 4 + 2) * XP];
        const float* xr3 = &xs[(rg * 4 + 3) * XP];
        const float* wp0 = &ws[gg * 6];

        #pragma unroll
        for (int hh = 0; hh < 2; ++hh) {
            __syncthreads();
            for (int idx = tid; idx < KT * (NC / 4); idx += 256) {
                int k = idx / (NC / 4), g4 = idx - k * (NC / 4);
                float4 v = *(const float4*)&WT[(size_t)(hh * KT + k) * G3 + c * NC + g4 * 4];
                *(float4*)&ws[k * WP2 + g4 * 4] = v;
            }
            __syncthreads();

            const int kb = hh * KT;
            #pragma unroll 4
            for (int k = 0; k < KT; ++k) {
                u64 x0 = splat2(__float_as_uint(xr0[kb + k]));
                u64 x1 = splat2(__float_as_uint(xr1[kb + k]));
                u64 x2 = splat2(__float_as_uint(xr2[kb + k]));
                u64 x3 = splat2(__float_as_uint(xr3[kb + k]));
                const u64* wrow = (const u64*)&wp0[k * WP2];
                u64 w01 = wrow[0], w23 = wrow[1], w45 = wrow[2];
                fma2(acc[0][0], x0, w01); fma2(acc[0][1], x0, w23); fma2(acc[0][2], x0, w45);
                fma2(acc[1][0], x1, w01); fma2(acc[1][1], x1, w23); fma2(acc[1][2], x1, w45);
                fma2(acc[2][0], x2, w01); fma2(acc[2][1], x2, w23); fma2(acc[2][2], x2, w45);
                fma2(acc[3][0], x3, w01); fma2(acc[3][1], x3, w23); fma2(acc[3][2], x3, w45);
            }
        }

        __syncthreads();

        const int g0 = c * NC + gg * 6;
        #pragma unroll
        for (int p = 0; p < 3; ++p) {
            float b0 = bias[g0 + 2 * p];
            float b1 = bias[g0 + 2 * p + 1];
            #pragma unroll
            for (int i = 0; i < 4; ++i) {
                float2 v = unpack2(acc[i][p]);
                int r = rg * 4 + i;
                ws[r * NC + gg * 6 + 2 * p]     = v.x + b0;
                ws[r * NC + gg * 6 + 2 * p + 1] = v.y + b1;
            }
        }
        __syncthreads();

        #pragma unroll
        for (int v = 0; v < (TM * NC / 4) / 256; ++v) {
            int idx = (v * 256 + tid) * 4;
            int r = idx / NC, col = idx - r * NC;
            float4 val = *(const float4*)&ws[idx];
            *(float4*)&out[(size_t)(rowbase + r) * G3 + c * NC + col] = val;
        }
    }
}

// ---------------------------------------------------------------------------
// Persistent GRU recurrence v16: R15 data path, PARTITIONED named barriers.
// Warp (jw = warp&3, q = warp>>2):
//   red visibility:  bar(1+jw, 128)  — the 4 warps sharing jw
//   h slice g:       bar(5+g, 224)   — producers {jw=g} + consumers {q=g}
// hs double-buffered (WAR removed); hprev carried in register.
// Matvec / reduction / gate code identical to R15.
// ---------------------------------------------------------------------------
template <int WRITE_SEQ>
__global__ __launch_bounds__(512, 1)
void gru_recurrent(const float* __restrict__ Whh,
                   const float* __restrict__ bhh)
{
    constexpr int RP = 13;

    extern __shared__ float sm[];
    float* Wn4 = sm;                     // [8][512][4] quad layout
    float* hs  = Wn4 + 8 * 512 * 4;      // [2][128][4] double-buffered
    float* red = hs + 2 * HDIM * 4;      // [4][128][RP]

    const int tid = threadIdx.x;
    const int j   = tid & 127;
    const int q   = tid >> 7;
    const int wrp_ = tid >> 5;
    const int jw  = wrp_ & 3;            // j-slice of this warp
    const int b0  = blockIdx.x * 4;
    const int k0  = q * 32;

    for (int idx = tid; idx < 8 * 512 * 4; idx += 512) {
        int kkg = idx >> 11;
        int rem = idx & 2047;
        int t2  = rem >> 2;
        int m   = rem & 3;
        int j2  = t2 & 127, q2 = t2 >> 7;
        int k2  = q2 * 32 + kkg * 4 + m;
        Wn4[idx] = Whh[(size_t)(2 * HDIM + j2) * HDIM + k2];
    }
    hs[tid] = 0.f;                       // zero buffer 0
    hs[512 + tid] = 0.f;                 // zero buffer 1

    unsigned int wrz[64];
    #pragma unroll
    for (int kk = 0; kk < 32; ++kk) {
        wrz[2 * kk]     = __float_as_uint(__ldg(Whh + (size_t)j * HDIM + k0 + kk));
        wrz[2 * kk + 1] = __float_as_uint(__ldg(Whh + (size_t)(HDIM + j) * HDIM + k0 + kk));
    }
    const float bhr = bhh[j];
    const float bhz = bhh[HDIM + j];
    const float bhn = bhh[2 * HDIM + j];

    __syncthreads();

    float* myred = &red[(q * HDIM + j) * RP];
    const float* gi = g_gi + (size_t)(b0 + q) * TDIM * G3;
    const uint4* wn4p = (const uint4*)Wn4 + tid;
    const int hb1 = 5 + (jw < q ? jw : q);      // ascending barrier ids
    const int hb2 = 5 + (jw < q ? q : jw);
    float hprev = 0.f;

    for (int t = 0; t < TDIM; ++t) {
        const ulonglong2* h16 = (const ulonglong2*)(hs + (t & 1) * 512);

        // Prefetch input-side preactivations (covered by the matvec).
        const float* gip = gi + (size_t)t * G3;
        float ir  = gip[j];
        float iz  = gip[HDIM + j];
        float in_ = gip[2 * HDIM + j];

        u64 a_r01 = 0, a_r23 = 0, a_z01 = 0, a_z23 = 0, a_n01 = 0, a_n23 = 0;

        #pragma unroll
        for (int kkg = 0; kkg < 8; ++kkg) {
            uint4 wq = wn4p[kkg * 512];
            #pragma unroll
            for (int m = 0; m < 4; ++m) {
                int kk = kkg * 4 + m;
                ulonglong2 hv = h16[k0 + kk];
                u64 wr2 = splat2(wrz[2 * kk]);
                u64 wz2 = splat2(wrz[2 * kk + 1]);
                unsigned int wnu = (m == 0) ? wq.x : (m == 1) ? wq.y
                                 : (m == 2) ? wq.z : wq.w;
                u64 wn2 = splat2(wnu);
                fma2(a_r01, wr2, hv.x); fma2(a_r23, wr2, hv.y);
                fma2(a_z01, wz2, hv.x); fma2(a_z23, wz2, hv.y);
                fma2(a_n01, wn2, hv.x); fma2(a_n23, wn2, hv.y);
            }
        }

        {
            float2 v;
            v = unpack2(a_r01); myred[0]  = v.x; myred[1]  = v.y;
            v = unpack2(a_r23); myred[2]  = v.x; myred[3]  = v.y;
            v = unpack2(a_z01); myred[4]  = v.x; myred[5]  = v.y;
            v = unpack2(a_z23); myred[6]  = v.x; myred[7]  = v.y;
            v = unpack2(a_n01); myred[8]  = v.x; myred[9]  = v.y;
            v = unpack2(a_n23); myred[10] = v.x; myred[11] = v.y;
        }
        NAMED_BAR(1 + jw, 128);          // red ready within the jw group

        // Gate phase: thread (j, q) finishes batch b = q.
        const int b = q;
        float sr = 0.f, sz = 0.f, sn = 0.f;
        #pragma unroll
        for (int qq = 0; qq < 4; ++qq) {
            const float* rp = &red[(qq * HDIM + j) * RP];
            sr += rp[0 * 4 + b];
            sz += rp[1 * 4 + b];
            sn += rp[2 * 4 + b];
        }
        float r = sigmoid_f(ir + sr + bhr);
        float z = sigmoid_f(iz + sz + bhz);
        float n = tanh_f(in_ + r * (sn + bhn));
        float hnew = n + z * (hprev - n);
        hprev = hnew;

        hs[((t + 1) & 1) * 512 + j * 4 + b] = hnew;
        if (WRITE_SEQ) {
            g_h1[((size_t)(b0 + b) * TDIM + t) * HDIM + j] = hnew;  // coalesced
        } else if (t == TDIM - 1) {
            g_hlast[(size_t)(b0 + b) * HDIM + j] = hnew;
        }

        // Partitioned h-slice barriers (ascending order; deadlock-free).
        NAMED_BAR(hb1, 224);
        if (hb2 != hb1) NAMED_BAR(hb2, 224);
    }
}

// ---------------------------------------------------------------------------
// Final FC (O = 1): one warp per batch.
// ---------------------------------------------------------------------------
__global__ void fc_kernel(const float* __restrict__ Wfc,
                          const float* __restrict__ bfc,
                          float* __restrict__ out)
{
    int w = (blockIdx.x * blockDim.x + threadIdx.x) >> 5;
    int lane = threadIdx.x & 31;
    if (w >= BDIM) return;
    const float* hp = g_hlast + (size_t)w * HDIM;
    float s = 0.f;
    #pragma unroll
    for (int k = lane; k < HDIM; k += 32) s += hp[k] * Wfc[k];
    #pragma unroll
    for (int o = 16; o; o >>= 1) s += __shfl_xor_sync(0xFFFFFFFFu, s, o);
    if (lane == 0) out[w] = s + bfc[0];
}

// ---------------------------------------------------------------------------
extern "C" void kernel_launch(void* const* d_in, const int* in_sizes, int n_in,
                              void* d_out, int out_size)
{
    const float* x     = (const float*)d_in[0];
    const float* W_ih0 = (const float*)d_in[1];
    const float* W_hh0 = (const float*)d_in[2];
    const float* b_ih0 = (const float*)d_in[3];
    const float* b_hh0 = (const float*)d_in[4];
    const float* W_ih1 = (const float*)d_in[5];
    const float* W_hh1 = (const float*)d_in[6];
    const float* b_ih1 = (const float*)d_in[7];
    const float* b_hh1 = (const float*)d_in[8];
    const float* W_fc  = (const float*)d_in[9];
    const float* b_fc  = (const float*)d_in[10];
    float* out = (float*)d_out;

    const int SMEM_G64  = (64 * 68  + 64 * 100) * 4;    // 43,008 B -> 5 CTAs
    const int SMEM_G128 = (64 * 132 + 64 * 100) * 4;    // 59,392 B -> 3 CTAs
    const int SMEM_REC  = (8 * 512 * 4 + 2 * HDIM * 4 + 4 * HDIM * 13) * 4; // 96,256 B

    cudaFuncSetAttribute(gi_gemm64,  cudaFuncAttributeMaxDynamicSharedMemorySize, SMEM_G64);
    cudaFuncSetAttribute(gi_gemm128, cudaFuncAttributeMaxDynamicSharedMemorySize, SMEM_G128);
    cudaFuncSetAttribute(gru_recurrent<1>, cudaFuncAttributeMaxDynamicSharedMemorySize, SMEM_REC);
    cudaFuncSetAttribute(gru_recurrent<0>, cudaFuncAttributeMaxDynamicSharedMemorySize, SMEM_REC);

    void* h1ptr = nullptr;
    cudaGetSymbolAddress(&h1ptr, g_h1);
    void* wt0ptr = nullptr;
    cudaGetSymbolAddress(&wt0ptr, g_WT0);
    void* wt1ptr = nullptr;
    cudaGetSymbolAddress(&wt1ptr, g_WT1);

    const int M = BDIM * TDIM;
    const int GEMM_GRID = M / 64;

    transpose_w<64> <<<(G3 * 64  + 255) / 256, 256>>>(W_ih0, (float*)wt0ptr);
    transpose_w<128><<<(G3 * 128 + 255) / 256, 256>>>(W_ih1, (float*)wt1ptr);

    gi_gemm64<<<GEMM_GRID, 256, SMEM_G64>>>(x, (const float*)wt0ptr, b_ih0);
    gru_recurrent<1><<<BDIM / 4, 512, SMEM_REC>>>(W_hh0, b_hh0);
    gi_gemm128<<<GEMM_GRID, 256, SMEM_G128>>>((const float*)h1ptr, (const float*)wt1ptr, b_ih1);
    gru_recurrent<0><<<BDIM / 4, 512, SMEM_REC>>>(W_hh1, b_hh1);
    fc_kernel<<<BDIM / 4, 128>>>(W_fc, b_fc, out);
}

// round 17
// speedup vs baseline: 1.0256x; 1.0256x over previous
#include <cuda_runtime.h>
#include <math.h>

#define BDIM 512
#define TDIM 512
#define IN0  64
#define HDIM 128
#define G3   384   // 3*H  (gate order r, z, n)

typedef unsigned long long u64;

// ---------------------------------------------------------------------------
// f32x2 packed helpers
// ---------------------------------------------------------------------------
__device__ __forceinline__ u64 splat2(unsigned int v) {
    u64 r; asm("mov.b64 %0, {%1, %1};" : "=l"(r) : "r"(v)); return r;
}
__device__ __forceinline__ void fma2(u64& d, u64 a, u64 b) {
    asm("fma.rn.f32x2 %0, %1, %2, %0;" : "+l"(d) : "l"(a), "l"(b));
}
__device__ __forceinline__ float2 unpack2(u64 v) {
    unsigned int lo, hi;
    asm("mov.b64 {%0, %1}, %2;" : "=r"(lo), "=r"(hi) : "l"(v));
    float2 f; f.x = __uint_as_float(lo); f.y = __uint_as_float(hi); return f;
}
__device__ __forceinline__ float sigmoid_f(float x) {
    return __fdividef(1.f, 1.f + __expf(-x));
}
__device__ __forceinline__ float tanh_f(float x) {
    // 2*sigmoid(2x) - 1 : short MUFU chain, rel err ~1e-6 (validated)
    return __fmaf_rn(2.f, __fdividef(1.f, 1.f + __expf(-2.f * x)), -1.f);
}

// ---------------------------------------------------------------------------
// Scratch
// ---------------------------------------------------------------------------
__device__ float g_gi [(size_t)BDIM * TDIM * G3];
__device__ float g_h1 [(size_t)BDIM * TDIM * HDIM];
__device__ float g_hlast[(size_t)BDIM * HDIM];
__device__ float g_WT0[64  * G3];    // W_ih0 transposed: [K][384]
__device__ float g_WT1[128 * G3];    // W_ih1 transposed: [K][384]

// ---------------------------------------------------------------------------
// One-time W_ih transpose: WT[k][g] = W[g][k].
// ---------------------------------------------------------------------------
template <int K>
__global__ void transpose_w(const float* __restrict__ W, float* __restrict__ WT)
{
    int idx = blockIdx.x * blockDim.x + threadIdx.x;
    if (idx >= G3 * K) return;
    int g = idx / K, k = idx - g * K;
    WT[k * G3 + g] = W[idx];
}

// ---------------------------------------------------------------------------
// gi GEMM v17: thread tile = 8 rows x 6 gates, 128 threads/CTA (TM=64).
// Inner loop per k: 8 x-LDS + 8 splats + 3 LDS.64 (w) + 24 FFMA2 ->
// non-fma:fma ratio halved vs R9 (19/48 vs 11/24). Same smem layouts,
// same CTAs/SM; reg cap 255 at 128 threads (no RF wall).
// KHALF=1: W staged in two 64-k halves (K=128 path, keeps smem at 59 KB).
// ---------------------------------------------------------------------------
template <int K, int KHALF>
__global__ __launch_bounds__(128)
void gi_gemm(const float* __restrict__ X,
             const float* __restrict__ WT,   // [K][384] transposed
             const float* __restrict__ bias)
{
    constexpr int TM  = 64;
    constexpr int NC  = 96;
    constexpr int KT  = KHALF ? 64 : K;    // W staging tile
    constexpr int NH  = K / KT;
    constexpr int XP  = K + 4;
    constexpr int WP2 = 100;

    extern __shared__ float sm[];
    float* xs = sm;               // [TM][XP] row-major, staged once
    float* ws = sm + TM * XP;     // [KT][WP2]; reused as [64][96] staging

    const int tid = threadIdx.x;
    const int rowbase = blockIdx.x * TM;

    // Stage full X tile once (float4 in/out, coalesced).
    for (int idx = tid; idx < TM * (K / 4); idx += 128) {
        int r = idx / (K / 4), kb = idx - r * (K / 4);
        float4 v = *(const float4*)&X[(size_t)(rowbase + r) * K + kb * 4];
        *(float4*)&xs[r * XP + kb * 4] = v;
    }

    const int rg = tid >> 4;      // 0..7  : row group (8 rows)
    const int gg = tid & 15;      // 0..15 : gate group (6 gates)
    float* out = g_gi;

    for (int c = 0; c < 4; ++c) {
        u64 acc[8][3];
        #pragma unroll
        for (int i = 0; i < 8; ++i)
            #pragma unroll
            for (int p = 0; p < 3; ++p) acc[i][p] = 0ull;

        const float* wp0 = &ws[gg * 6];

        #pragma unroll
        for (int hh = 0; hh < NH; ++hh) {
            __syncthreads();   // previous readers of ws done
            // Stage W tile from transposed global: coalesced float4.
            for (int idx = tid; idx < KT * (NC / 4); idx += 128) {
                int k = idx / (NC / 4), g4 = idx - k * (NC / 4);
                float4 v = *(const float4*)&WT[(size_t)(hh * KT + k) * G3 + c * NC + g4 * 4];
                *(float4*)&ws[k * WP2 + g4 * 4] = v;
            }
            __syncthreads();

            const int kb = hh * KT;
            #pragma unroll 4
            for (int k = 0; k < KT; ++k) {
                const u64* wrow = (const u64*)&wp0[k * WP2];
                u64 w01 = wrow[0], w23 = wrow[1], w45 = wrow[2];
                #pragma unroll
                for (int i = 0; i < 8; ++i) {
                    u64 xi = splat2(__float_as_uint(xs[(rg * 8 + i) * XP + kb + k]));
                    fma2(acc[i][0], xi, w01);
                    fma2(acc[i][1], xi, w23);
                    fma2(acc[i][2], xi, w45);
                }
            }
        }

        __syncthreads();  // done reading ws; reuse as output staging

        const int g0 = c * NC + gg * 6;
        #pragma unroll
        for (int p = 0; p < 3; ++p) {
            float b0 = bias[g0 + 2 * p];
            float b1 = bias[g0 + 2 * p + 1];
            #pragma unroll
            for (int i = 0; i < 8; ++i) {
                float2 v = unpack2(acc[i][p]);
                int r = rg * 8 + i;
                ws[r * NC + gg * 6 + 2 * p]     = v.x + b0;
                ws[r * NC + gg * 6 + 2 * p + 1] = v.y + b1;
            }
        }
        __syncthreads();

        #pragma unroll
        for (int v = 0; v < (TM * NC / 4) / 128; ++v) {
            int idx = (v * 128 + tid) * 4;
            int r = idx / NC, col = idx - r * NC;
            float4 val = *(const float4*)&ws[idx];
            *(float4*)&out[(size_t)(rowbase + r) * G3 + c * NC + col] = val;
        }
    }
}

// ---------------------------------------------------------------------------
// Persistent GRU recurrence (R15-exact, best measured: 672 us).
// ---------------------------------------------------------------------------
template <int WRITE_SEQ>
__global__ __launch_bounds__(512, 1)
void gru_recurrent(const float* __restrict__ Whh,
                   const float* __restrict__ bhh)
{
    constexpr int RP = 13;

    extern __shared__ float sm[];
    float* Wn4 = sm;                     // [8][512][4] quad layout
    float* hs  = Wn4 + 8 * 512 * 4;      // [128][4], 16B-aligned
    float* red = hs + HDIM * 4;          // [4][128][RP]

    const int tid = threadIdx.x;
    const int j   = tid & 127;
    const int q   = tid >> 7;
    const int b0  = blockIdx.x * 4;
    const int k0  = q * 32;

    for (int idx = tid; idx < 8 * 512 * 4; idx += 512) {
        int kkg = idx >> 11;
        int rem = idx & 2047;
        int t2  = rem >> 2;
        int m   = rem & 3;
        int j2  = t2 & 127, q2 = t2 >> 7;
        int k2  = q2 * 32 + kkg * 4 + m;
        Wn4[idx] = Whh[(size_t)(2 * HDIM + j2) * HDIM + k2];
    }
    hs[tid & 511] = 0.f;

    unsigned int wrz[64];
    #pragma unroll
    for (int kk = 0; kk < 32; ++kk) {
        wrz[2 * kk]     = __float_as_uint(__ldg(Whh + (size_t)j * HDIM + k0 + kk));
        wrz[2 * kk + 1] = __float_as_uint(__ldg(Whh + (size_t)(HDIM + j) * HDIM + k0 + kk));
    }
    const float bhr = bhh[j];
    const float bhz = bhh[HDIM + j];
    const float bhn = bhh[2 * HDIM + j];

    __syncthreads();

    float* myred = &red[(q * HDIM + j) * RP];
    const float* gi = g_gi + (size_t)(b0 + q) * TDIM * G3;
    const ulonglong2* h16 = (const ulonglong2*)hs;
    const uint4* wn4p = (const uint4*)Wn4 + tid;

    for (int t = 0; t < TDIM; ++t) {
        const float* gip = gi + (size_t)t * G3;
        float ir  = gip[j];
        float iz  = gip[HDIM + j];
        float in_ = gip[2 * HDIM + j];

        u64 a_r01 = 0, a_r23 = 0, a_z01 = 0, a_z23 = 0, a_n01 = 0, a_n23 = 0;

        #pragma unroll
        for (int kkg = 0; kkg < 8; ++kkg) {
            uint4 wq = wn4p[kkg * 512];
            #pragma unroll
            for (int m = 0; m < 4; ++m) {
                int kk = kkg * 4 + m;
                ulonglong2 hv = h16[k0 + kk];
                u64 wr2 = splat2(wrz[2 * kk]);
                u64 wz2 = splat2(wrz[2 * kk + 1]);
                unsigned int wnu = (m == 0) ? wq.x : (m == 1) ? wq.y
                                 : (m == 2) ? wq.z : wq.w;
                u64 wn2 = splat2(wnu);
                fma2(a_r01, wr2, hv.x); fma2(a_r23, wr2, hv.y);
                fma2(a_z01, wz2, hv.x); fma2(a_z23, wz2, hv.y);
                fma2(a_n01, wn2, hv.x); fma2(a_n23, wn2, hv.y);
            }
        }

        {
            float2 v;
            v = unpack2(a_r01); myred[0]  = v.x; myred[1]  = v.y;
            v = unpack2(a_r23); myred[2]  = v.x; myred[3]  = v.y;
            v = unpack2(a_z01); myred[4]  = v.x; myred[5]  = v.y;
            v = unpack2(a_z23); myred[6]  = v.x; myred[7]  = v.y;
            v = unpack2(a_n01); myred[8]  = v.x; myred[9]  = v.y;
            v = unpack2(a_n23); myred[10] = v.x; myred[11] = v.y;
        }
        __syncthreads();

        const int b = q;
        float sr = 0.f, sz = 0.f, sn = 0.f;
        #pragma unroll
        for (int qq = 0; qq < 4; ++qq) {
            const float* rp = &red[(qq * HDIM + j) * RP];
            sr += rp[0 * 4 + b];
            sz += rp[1 * 4 + b];
            sn += rp[2 * 4 + b];
        }
        float r = sigmoid_f(ir + sr + bhr);
        float z = sigmoid_f(iz + sz + bhz);
        float n = tanh_f(in_ + r * (sn + bhn));
        float hold = hs[j * 4 + b];
        float hnew = n + z * (hold - n);

        hs[j * 4 + b] = hnew;
        if (WRITE_SEQ) {
            g_h1[((size_t)(b0 + b) * TDIM + t) * HDIM + j] = hnew;
        } else if (t == TDIM - 1) {
            g_hlast[(size_t)(b0 + b) * HDIM + j] = hnew;
        }
        __syncthreads();
    }
}

// ---------------------------------------------------------------------------
// Final FC (O = 1): one warp per batch.
// ---------------------------------------------------------------------------
__global__ void fc_kernel(const float* __restrict__ Wfc,
                          const float* __restrict__ bfc,
                          float* __restrict__ out)
{
    int w = (blockIdx.x * blockDim.x + threadIdx.x) >> 5;
    int lane = threadIdx.x & 31;
    if (w >= BDIM) return;
    const float* hp = g_hlast + (size_t)w * HDIM;
    float s = 0.f;
    #pragma unroll
    for (int k = lane; k < HDIM; k += 32) s += hp[k] * Wfc[k];
    #pragma unroll
    for (int o = 16; o; o >>= 1) s += __shfl_xor_sync(0xFFFFFFFFu, s, o);
    if (lane == 0) out[w] = s + bfc[0];
}

// ---------------------------------------------------------------------------
extern "C" void kernel_launch(void* const* d_in, const int* in_sizes, int n_in,
                              void* d_out, int out_size)
{
    const float* x     = (const float*)d_in[0];
    const float* W_ih0 = (const float*)d_in[1];
    const float* W_hh0 = (const float*)d_in[2];
    const float* b_ih0 = (const float*)d_in[3];
    const float* b_hh0 = (const float*)d_in[4];
    const float* W_ih1 = (const float*)d_in[5];
    const float* W_hh1 = (const float*)d_in[6];
    const float* b_ih1 = (const float*)d_in[7];
    const float* b_hh1 = (const float*)d_in[8];
    const float* W_fc  = (const float*)d_in[9];
    const float* b_fc  = (const float*)d_in[10];
    float* out = (float*)d_out;

    const int SMEM_G64  = (64 * 68  + 64 * 100) * 4;    // 43,008 B
    const int SMEM_G128 = (64 * 132 + 64 * 100) * 4;    // 59,392 B
    const int SMEM_REC  = (8 * 512 * 4 + HDIM * 4 + 4 * HDIM * 13) * 4; // 94,208 B

    cudaFuncSetAttribute((const void*)gi_gemm<64, 0>,
                         cudaFuncAttributeMaxDynamicSharedMemorySize, SMEM_G64);
    cudaFuncSetAttribute((const void*)gi_gemm<128, 1>,
                         cudaFuncAttributeMaxDynamicSharedMemorySize, SMEM_G128);
    cudaFuncSetAttribute(gru_recurrent<1>, cudaFuncAttributeMaxDynamicSharedMemorySize, SMEM_REC);
    cudaFuncSetAttribute(gru_recurrent<0>, cudaFuncAttributeMaxDynamicSharedMemorySize, SMEM_REC);

    void* h1ptr = nullptr;
    cudaGetSymbolAddress(&h1ptr, g_h1);
    void* wt0ptr = nullptr;
    cudaGetSymbolAddress(&wt0ptr, g_WT0);
    void* wt1ptr = nullptr;
    cudaGetSymbolAddress(&wt1ptr, g_WT1);

    const int M = BDIM * TDIM;
    const int GEMM_GRID = M / 64;

    transpose_w<64> <<<(G3 * 64  + 255) / 256, 256>>>(W_ih0, (float*)wt0ptr);
    transpose_w<128><<<(G3 * 128 + 255) / 256, 256>>>(W_ih1, (float*)wt1ptr);

    gi_gemm<64, 0><<<GEMM_GRID, 128, SMEM_G64>>>(x, (const float*)wt0ptr, b_ih0);
    gru_recurrent<1><<<BDIM / 4, 512, SMEM_REC>>>(W_hh0, b_hh0);
    gi_gemm<128, 1><<<GEMM_GRID, 128, SMEM_G128>>>((const float*)h1ptr, (const float*)wt1ptr, b_ih1);
    gru_recurrent<0><<<BDIM / 4, 512, SMEM_REC>>>(W_hh1, b_hh1);
    fc_kernel<<<BDIM / 4, 128>>>(W_fc, b_fc, out);
}